// round 12
// baseline (speedup 1.0000x reference)
#include <cuda_runtime.h>
#include <cstdint>

// ---------------- problem constants ----------------
#define BATCH 256
#define HW    147456            // 384*384 px per sample
#define NB    4096              // coarse histogram bins (bin = q >> 4)
#define QSCALE 65535.0f

// target order-statistic ranks (0-based): q*(n-1) = 14745.5 / 132709.5
#define KL 14745
#define KH 132709

// K1 geometry: 4 blocks/sample, 1024 threads, 36 px/thread
#define TPB1   1024
#define BPS1   4
#define PXB1   (HW / BPS1)            // 36864 px per block
#define ITER1  (PXB1 / (TPB1 * 4))    // 9 iterations of 4 px

// K3 geometry: 4 blocks/sample, 1024 threads, 9 uint2/thread
#define TPB3   1024
#define BPS3   4
#define W3     (HW / 4 / BPS3 / TPB3) // 9

// K5 geometry: 9 blocks/sample, 512 threads, 8 float4 (32 px) per thread
#define TPB5   512
#define F4PT   8
#define PXB5   (TPB5 * F4PT * 4)      // 16384 px per block
#define BPS5   (HW / PXB5)            // 9 blocks per sample

// ---------------- device scratch (static, allocation-free, zero-init) -------
__device__ uint32_t g_xq[BATCH * HW / 2];   // packed u16 means, 75 MB
__device__ int      g_hist[BATCH * NB];     // per-sample hist (self-cleaned)
__device__ int      g_windat[BATCH][6];     // loMin, loMax, hiMin, hiMax, cum0, cum1
__device__ int      g_sub[64][BATCH];       // sub-hist, transposed (self-cleaned)
__device__ int      g_c1[BATCH], g_c3[BATCH];  // arrival counters (self-reset)
__device__ float2   g_ab[BATCH];            // loQ, invQ

// ---- K1: stream x, quantize u16, write xq, coarse hist; last block scans ---
__global__ void __launch_bounds__(TPB1) k1_quant_hist(const float* __restrict__ x) {
    __shared__ int sh[NB];
    __shared__ int s_warp[32];
    __shared__ int s_role;
    const int s     = blockIdx.x >> 2;
    const int chunk = blockIdx.x & (BPS1 - 1);
    const int t     = threadIdx.x;
    const int lane  = t & 31;
    const int wid   = t >> 5;

    for (int i = t; i < NB; i += TPB1) sh[i] = 0;
    __syncthreads();

    const int base = s * HW + chunk * PXB1;
    const float4* __restrict__ xin = (const float4*)x;
    const float third = 1.0f / 3.0f;

#pragma unroll 3
    for (int it = 0; it < ITER1; ++it) {
        int p  = base + it * (TPB1 * 4) + t * 4;
        int f4 = (p * 3) >> 2;
        float4 a = __ldcs(xin + f4 + 0);   // stream x: don't pollute L2
        float4 b = __ldcs(xin + f4 + 1);
        float4 c = __ldcs(xin + f4 + 2);

        uint32_t q0 = min((uint32_t)((a.x + a.y + a.z) * third * QSCALE + 0.5f), 65535u);
        uint32_t q1 = min((uint32_t)((a.w + b.x + b.y) * third * QSCALE + 0.5f), 65535u);
        uint32_t q2 = min((uint32_t)((b.z + b.w + c.x) * third * QSCALE + 0.5f), 65535u);
        uint32_t q3 = min((uint32_t)((c.y + c.z + c.w) * third * QSCALE + 0.5f), 65535u);

        uint2 w; w.x = q0 | (q1 << 16); w.y = q2 | (q3 << 16);
        ((uint2*)g_xq)[p >> 2] = w;        // retain in L2 for K3/K5

        atomicAdd(&sh[q0 >> 4], 1);
        atomicAdd(&sh[q1 >> 4], 1);
        atomicAdd(&sh[q2 >> 4], 1);
        atomicAdd(&sh[q3 >> 4], 1);
    }
    __syncthreads();

    int* gh = &g_hist[s * NB];
    for (int i = t; i < NB; i += TPB1) {
        int v = sh[i];
        if (v) atomicAdd(&gh[i], v);
    }

    // -------- last-arriving block of this sample scans the histogram --------
    __threadfence();                       // release our hist flush
    if (t == 0) s_role = atomicAdd(&g_c1[s], 1);
    __syncthreads();
    if (s_role != BPS1 - 1) return;

    __threadfence();                       // acquire siblings' flushes
    int4 cw = *(int4*)(gh + 4 * t);
    *(int4*)(gh + 4 * t) = make_int4(0, 0, 0, 0);   // self-clean for replay
    int cnt[4] = {cw.x, cw.y, cw.z, cw.w};
    int local = cnt[0] + cnt[1] + cnt[2] + cnt[3];

    int v = local;
#pragma unroll
    for (int o = 1; o < 32; o <<= 1) {
        int n = __shfl_up_sync(0xFFFFFFFFu, v, o);
        if (lane >= o) v += n;
    }
    if (lane == 31) s_warp[wid] = v;
    __syncthreads();
    if (wid == 0) {
        int wv = s_warp[lane];
#pragma unroll
        for (int o = 1; o < 32; o <<= 1) {
            int n = __shfl_up_sync(0xFFFFFFFFu, wv, o);
            if (lane >= o) wv += n;
        }
        s_warp[lane] = wv;
    }
    __syncthreads();
    int cum = (v - local) + (wid ? s_warp[wid - 1] : 0);

    const int targets[4] = {KL, KL + 1, KH, KH + 1};
#pragma unroll
    for (int i = 0; i < 4; i++) {
        int c = cnt[i];
        int bin = 4 * t + i;
#pragma unroll
        for (int k = 0; k < 4; k++) {
            int r = targets[k];
            if (cum <= r && r < cum + c) {
                if (k == 0) { g_windat[s][0] = bin; g_windat[s][4] = cum; }
                if (k == 1) { g_windat[s][1] = bin; }
                if (k == 2) { g_windat[s][2] = bin; g_windat[s][5] = cum; }
                if (k == 3) { g_windat[s][3] = bin; }
            }
        }
        cum += c;
    }
    if (t == 0) g_c1[s] = 0;               // reset counter for graph replay
}

// ---- K3: stream xq (L2-hot), scatter window hits; last block selects -------
__global__ void __launch_bounds__(TPB3) k3_gather() {
    __shared__ int s_role;
    const int s     = blockIdx.x >> 2;
    const int chunk = blockIdx.x & (BPS3 - 1);
    const int t     = threadIdx.x;

    const int loMin = g_windat[s][0], loMax = g_windat[s][1];
    const int hiMin = g_windat[s][2], hiMax = g_windat[s][3];

    const uint2* __restrict__ xq2 =
        (const uint2*)g_xq + (size_t)s * (HW / 4) + chunk * (TPB3 * W3);

#pragma unroll
    for (int k = 0; k < W3; k++) {
        uint2 w = xq2[k * TPB3 + t];
        uint32_t qs[4] = {w.x & 0xFFFFu, w.x >> 16, w.y & 0xFFFFu, w.y >> 16};
#pragma unroll
        for (int i = 0; i < 4; i++) {
            uint32_t q = qs[i];
            int b = (int)(q >> 4);
            if (b == loMin)      atomicAdd(&g_sub[q & 15][s], 1);
            else if (b == loMax) atomicAdd(&g_sub[16 + (q & 15)][s], 1);
            if (b == hiMin)      atomicAdd(&g_sub[32 + (q & 15)][s], 1);
            else if (b == hiMax) atomicAdd(&g_sub[48 + (q & 15)][s], 1);
        }
    }

    // -------- last-arriving block of this sample selects the quantiles ------
    __threadfence();
    if (t == 0) s_role = atomicAdd(&g_c3[s], 1);
    __syncthreads();
    if (s_role != BPS3 - 1) return;
    __threadfence();

    if (t == 0) {
        int sub[64];
#pragma unroll
        for (int i = 0; i < 64; i++) { sub[i] = g_sub[i][s]; g_sub[i][s] = 0; }

        float vsel[4];
        // lo quantile: ranks KL, KL+1
        {
            int t0 = KL - g_windat[s][4];
            int cum = 0, found = 0;
            for (int g = 0; g < 2 && found < 2; g++) {
                if (g == 1 && loMax == loMin) break;
                int binv = (g ? loMax : loMin) << 4;
                for (int i = 0; i < 16 && found < 2; i++) {
                    int c = sub[g * 16 + i];
                    if (found == 0 && cum <= t0 && t0 < cum + c) { vsel[0] = (float)(binv + i); found = 1; }
                    if (found <= 1 && cum <= t0 + 1 && t0 + 1 < cum + c) { vsel[1] = (float)(binv + i); found = 2; }
                    cum += c;
                }
            }
        }
        // hi quantile: ranks KH, KH+1
        {
            int t0 = KH - g_windat[s][5];
            int cum = 0, found = 0;
            for (int g = 0; g < 2 && found < 2; g++) {
                if (g == 1 && hiMax == hiMin) break;
                int binv = (g ? hiMax : hiMin) << 4;
                for (int i = 0; i < 16 && found < 2; i++) {
                    int c = sub[32 + g * 16 + i];
                    if (found == 0 && cum <= t0 && t0 < cum + c) { vsel[2] = (float)(binv + i); found = 1; }
                    if (found <= 1 && cum <= t0 + 1 && t0 + 1 < cum + c) { vsel[3] = (float)(binv + i); found = 2; }
                    cum += c;
                }
            }
        }

        float loQ = 0.5f * (vsel[0] + vsel[1]);
        float hiQ = 0.5f * (vsel[2] + vsel[3]);
        float rngQ = fmaxf(hiQ - loQ, 1e-6f * QSCALE);
        g_ab[s] = make_float2(loQ, 1.0f / rngQ);
        g_c3[s] = 0;                        // reset counter for graph replay
    }
}

// ---- K5: normalize + clip; xq read mostly L2-hot, streamed output ----------
__global__ void __launch_bounds__(TPB5) k5_norm(float* __restrict__ out) {
    const int s     = blockIdx.x / BPS5;
    const int chunk = blockIdx.x % BPS5;
    const int t     = threadIdx.x;

    float2 ab = g_ab[s];
    const float loQ  = ab.x;
    const float invQ = ab.y;

    const uint2* __restrict__ xq2 =
        (const uint2*)g_xq + (size_t)s * (HW / 4) + chunk * (TPB5 * F4PT);
    float4* __restrict__ o4 =
        (float4*)out + (size_t)s * (HW / 4) + chunk * (TPB5 * F4PT);

#pragma unroll
    for (int k = 0; k < F4PT; k++) {
        uint2 w = __ldcs(xq2 + k * TPB5 + t);   // last use of xq
        float4 r;
        r.x = __saturatef(((float)(w.x & 0xFFFFu) - loQ) * invQ);
        r.y = __saturatef(((float)(w.x >> 16)     - loQ) * invQ);
        r.z = __saturatef(((float)(w.y & 0xFFFFu) - loQ) * invQ);
        r.w = __saturatef(((float)(w.y >> 16)     - loQ) * invQ);
        __stcs(o4 + k * TPB5 + t, r);
    }
}

// ---------------- launch ----------------
extern "C" void kernel_launch(void* const* d_in, const int* in_sizes, int n_in,
                              void* d_out, int out_size) {
    const float* x = (const float*)d_in[0];
    float* out = (float*)d_out;

    k1_quant_hist<<<BATCH * BPS1, TPB1>>>(x);
    k3_gather<<<BATCH * BPS3, TPB3>>>();
    k5_norm<<<BATCH * BPS5, TPB5>>>(out);
}

// round 13
// speedup vs baseline: 1.0897x; 1.0897x over previous
#include <cuda_runtime.h>
#include <cstdint>

// ---------------- problem constants ----------------
#define BATCH 256
#define HW    147456            // 384*384 px per sample
#define NB    4096              // coarse histogram bins (bin = q >> 4)
#define QSCALE 65535.0f

// target order-statistic ranks (0-based): q*(n-1) = 14745.5 / 132709.5
#define KL 14745
#define KH 132709

// K1 geometry: 4 blocks/sample, 1024 threads, 36 px/thread
#define TPB1   1024
#define BPS1   4
#define PXB1   (HW / BPS1)            // 36864 px per block
#define ITER1  (PXB1 / (TPB1 * 4))    // 9 iterations of 4 px

// K3 geometry: 4 blocks/sample, 1024 threads, 9 uint2/thread
#define TPB3   1024
#define BPS3   4
#define W3     (HW / 4 / BPS3 / TPB3) // 9

// K5 geometry: 9 blocks/sample, 512 threads, 8 float4 (32 px) per thread
#define TPB5   512
#define F4PT   8
#define PXB5   (TPB5 * F4PT * 4)      // 16384 px per block
#define BPS5   (HW / PXB5)            // 9 blocks per sample

// ---------------- device scratch (static, allocation-free, zero-init) -------
__device__ uint32_t g_xq[BATCH * HW / 2];   // packed u16 means, 75 MB
__device__ int      g_hist[BATCH * NB];     // per-sample hist (cleaned by K3 epilogue)
__device__ int      g_sub[64][BATCH];       // sub-hist, transposed (cleaned by K3 epilogue)
__device__ int      g_c3[BATCH];            // arrival counters (self-reset)
__device__ float2   g_ab[BATCH];            // loQ, invQ

// ---- K1: stream x, channel-mean, quantize u16, write xq, coarse hist -------
// (clean R9 version: no fences, no epilogue — runs at the BW ceiling)
__global__ void __launch_bounds__(TPB1) k1_quant_hist(const float* __restrict__ x) {
    __shared__ int sh[NB];
    const int s     = blockIdx.x >> 2;
    const int chunk = blockIdx.x & (BPS1 - 1);
    const int t     = threadIdx.x;

    for (int i = t; i < NB; i += TPB1) sh[i] = 0;
    __syncthreads();

    const int base = s * HW + chunk * PXB1;
    const float4* __restrict__ xin = (const float4*)x;
    const float third = 1.0f / 3.0f;

#pragma unroll 3
    for (int it = 0; it < ITER1; ++it) {
        int p  = base + it * (TPB1 * 4) + t * 4;
        int f4 = (p * 3) >> 2;
        float4 a = __ldcs(xin + f4 + 0);   // stream x: don't pollute L2
        float4 b = __ldcs(xin + f4 + 1);
        float4 c = __ldcs(xin + f4 + 2);

        uint32_t q0 = min((uint32_t)((a.x + a.y + a.z) * third * QSCALE + 0.5f), 65535u);
        uint32_t q1 = min((uint32_t)((a.w + b.x + b.y) * third * QSCALE + 0.5f), 65535u);
        uint32_t q2 = min((uint32_t)((b.z + b.w + c.x) * third * QSCALE + 0.5f), 65535u);
        uint32_t q3 = min((uint32_t)((c.y + c.z + c.w) * third * QSCALE + 0.5f), 65535u);

        uint2 w; w.x = q0 | (q1 << 16); w.y = q2 | (q3 << 16);
        ((uint2*)g_xq)[p >> 2] = w;        // retain in L2 for K3/K5

        atomicAdd(&sh[q0 >> 4], 1);
        atomicAdd(&sh[q1 >> 4], 1);
        atomicAdd(&sh[q2 >> 4], 1);
        atomicAdd(&sh[q3 >> 4], 1);
    }
    __syncthreads();

    int* gh = &g_hist[s * NB];
    for (int i = t; i < NB; i += TPB1) {
        int v = sh[i];
        if (v) atomicAdd(&gh[i], v);       // result unused -> REDG
    }
}

// ---- K3: per-block hist scan (redundant, L2-cheap) -> stream xq + scatter --
//      last-arriving block per sample: exact select + cleanup
__global__ void __launch_bounds__(TPB3) k3_gather_select() {
    __shared__ int s_warp[32];
    __shared__ int s_selBin[4], s_selCum[4];
    __shared__ int s_sub[64];
    __shared__ int s_role;

    const int s     = blockIdx.x >> 2;
    const int chunk = blockIdx.x & (BPS3 - 1);
    const int t     = threadIdx.x;
    const int lane  = t & 31;
    const int wid   = t >> 5;

    // ---- prologue: every block scans its sample's 16 KB histogram ----
    {
        const int* gh = &g_hist[s * NB];
        int4 cw = *(const int4*)(gh + 4 * t);        // read-only: siblings read too
        int cnt[4] = {cw.x, cw.y, cw.z, cw.w};
        int local = cnt[0] + cnt[1] + cnt[2] + cnt[3];

        int v = local;
#pragma unroll
        for (int o = 1; o < 32; o <<= 1) {
            int n = __shfl_up_sync(0xFFFFFFFFu, v, o);
            if (lane >= o) v += n;
        }
        if (lane == 31) s_warp[wid] = v;
        __syncthreads();
        if (wid == 0) {
            int wv = s_warp[lane];
#pragma unroll
            for (int o = 1; o < 32; o <<= 1) {
                int n = __shfl_up_sync(0xFFFFFFFFu, wv, o);
                if (lane >= o) wv += n;
            }
            s_warp[lane] = wv;
        }
        __syncthreads();
        int cum = (v - local) + (wid ? s_warp[wid - 1] : 0);

        const int targets[4] = {KL, KL + 1, KH, KH + 1};
#pragma unroll
        for (int i = 0; i < 4; i++) {
            int c = cnt[i];
#pragma unroll
            for (int k = 0; k < 4; k++) {
                int r = targets[k];
                if (cum <= r && r < cum + c) { s_selBin[k] = 4 * t + i; s_selCum[k] = cum; }
            }
            cum += c;
        }
    }
    __syncthreads();

    const int loMin = s_selBin[0], loMax = s_selBin[1];
    const int hiMin = s_selBin[2], hiMax = s_selBin[3];

    // ---- stream xq chunk (L2-hot), scatter window hits to global sub-hist --
    const uint2* __restrict__ xq2 =
        (const uint2*)g_xq + (size_t)s * (HW / 4) + chunk * (TPB3 * W3);

#pragma unroll
    for (int k = 0; k < W3; k++) {
        uint2 w = xq2[k * TPB3 + t];
        uint32_t qs[4] = {w.x & 0xFFFFu, w.x >> 16, w.y & 0xFFFFu, w.y >> 16};
#pragma unroll
        for (int i = 0; i < 4; i++) {
            uint32_t q = qs[i];
            int b = (int)(q >> 4);
            if (b == loMin)      atomicAdd(&g_sub[q & 15][s], 1);
            else if (b == loMax) atomicAdd(&g_sub[16 + (q & 15)][s], 1);
            if (b == hiMin)      atomicAdd(&g_sub[32 + (q & 15)][s], 1);
            else if (b == hiMax) atomicAdd(&g_sub[48 + (q & 15)][s], 1);
        }
    }

    // ---- arrival: fence covers only the ~80 scatter REDGs above (cheap) ----
    __threadfence();
    if (t == 0) s_role = atomicAdd(&g_c3[s], 1);
    __syncthreads();
    if (s_role != BPS3 - 1) return;
    __threadfence();                        // acquire siblings' scatters

    // ---- epilogue (last block only): exact select, then cleanup ----
    if (t < 64) s_sub[t] = g_sub[t][s];
    __syncthreads();

    if (t == 0) {
        float vsel[4];
        // lo quantile: ranks KL, KL+1
        {
            int t0 = KL - s_selCum[0];
            int cum = 0, found = 0;
            for (int g = 0; g < 2 && found < 2; g++) {
                if (g == 1 && loMax == loMin) break;
                int binv = (g ? loMax : loMin) << 4;
                for (int i = 0; i < 16 && found < 2; i++) {
                    int c = s_sub[g * 16 + i];
                    if (found == 0 && cum <= t0 && t0 < cum + c) { vsel[0] = (float)(binv + i); found = 1; }
                    if (found <= 1 && cum <= t0 + 1 && t0 + 1 < cum + c) { vsel[1] = (float)(binv + i); found = 2; }
                    cum += c;
                }
            }
        }
        // hi quantile: ranks KH, KH+1
        {
            int t0 = KH - s_selCum[2];
            int cum = 0, found = 0;
            for (int g = 0; g < 2 && found < 2; g++) {
                if (g == 1 && hiMax == hiMin) break;
                int binv = (g ? hiMax : hiMin) << 4;
                for (int i = 0; i < 16 && found < 2; i++) {
                    int c = s_sub[32 + g * 16 + i];
                    if (found == 0 && cum <= t0 && t0 < cum + c) { vsel[2] = (float)(binv + i); found = 1; }
                    if (found <= 1 && cum <= t0 + 1 && t0 + 1 < cum + c) { vsel[3] = (float)(binv + i); found = 2; }
                    cum += c;
                }
            }
        }

        float loQ = 0.5f * (vsel[0] + vsel[1]);
        float hiQ = 0.5f * (vsel[2] + vsel[3]);
        float rngQ = fmaxf(hiQ - loQ, 1e-6f * QSCALE);
        g_ab[s] = make_float2(loQ, 1.0f / rngQ);
    }

    // cleanup for graph replay (all siblings finished reading hist/sub by now)
    {
        int* gh = &g_hist[s * NB];
        *(int4*)(gh + 4 * t) = make_int4(0, 0, 0, 0);
        if (t < 64) g_sub[t][s] = 0;
        if (t == 0) g_c3[s] = 0;
    }
}

// ---- K5: normalize + clip; xq read mostly L2-hot, streamed output ----------
__global__ void __launch_bounds__(TPB5) k5_norm(float* __restrict__ out) {
    const int s     = blockIdx.x / BPS5;
    const int chunk = blockIdx.x % BPS5;
    const int t     = threadIdx.x;

    float2 ab = g_ab[s];
    const float loQ  = ab.x;
    const float invQ = ab.y;

    const uint2* __restrict__ xq2 =
        (const uint2*)g_xq + (size_t)s * (HW / 4) + chunk * (TPB5 * F4PT);
    float4* __restrict__ o4 =
        (float4*)out + (size_t)s * (HW / 4) + chunk * (TPB5 * F4PT);

#pragma unroll
    for (int k = 0; k < F4PT; k++) {
        uint2 w = __ldcs(xq2 + k * TPB5 + t);   // last use of xq
        float4 r;
        r.x = __saturatef(((float)(w.x & 0xFFFFu) - loQ) * invQ);
        r.y = __saturatef(((float)(w.x >> 16)     - loQ) * invQ);
        r.z = __saturatef(((float)(w.y & 0xFFFFu) - loQ) * invQ);
        r.w = __saturatef(((float)(w.y >> 16)     - loQ) * invQ);
        __stcs(o4 + k * TPB5 + t, r);
    }
}

// ---------------- launch ----------------
extern "C" void kernel_launch(void* const* d_in, const int* in_sizes, int n_in,
                              void* d_out, int out_size) {
    const float* x = (const float*)d_in[0];
    float* out = (float*)d_out;

    k1_quant_hist<<<BATCH * BPS1, TPB1>>>(x);
    k3_gather_select<<<BATCH * BPS3, TPB3>>>();
    k5_norm<<<BATCH * BPS5, TPB5>>>(out);
}

// round 14
// speedup vs baseline: 1.2231x; 1.1224x over previous
#include <cuda_runtime.h>
#include <cstdint>

// ---------------- problem constants ----------------
#define BATCH 256
#define HW    147456            // 384*384 px per sample
#define NBF   16384             // fine histogram bins (bin = q >> 2)
#define QSCALE 65535.0f
#define SMEM_H (NBF * 4)        // 64 KB dynamic smem for K1 histogram

// target order-statistic ranks (0-based): q*(n-1) = 14745.5 / 132709.5
#define KL 14745
#define KH 132709

// K1 geometry: 4 blocks/sample, 1024 threads, 36 px/thread
#define TPB1   1024
#define BPS1   4
#define PXB1   (HW / BPS1)            // 36864 px per block
#define ITER1  (PXB1 / (TPB1 * 4))    // 9 iterations of 4 px

// K5 geometry: 9 blocks/sample, 512 threads, 8 float4 (32 px) per thread
#define TPB5   512
#define F4PT   8
#define PXB5   (TPB5 * F4PT * 4)      // 16384 px per block
#define BPS5   (HW / PXB5)            // 9 blocks per sample

// ---------------- device scratch (static, allocation-free, zero-init) -------
__device__ uint32_t g_xq[BATCH * HW / 2];   // packed u16 means, 75 MB
__device__ int      g_hist[BATCH * NBF];    // per-sample fine hist (cleaned by k2)
__device__ float2   g_ab[BATCH];            // loQ, invQ (u16-value units)

// ---- K1: stream x, channel-mean, quantize u16, write xq, fine hist ---------
__global__ void __launch_bounds__(TPB1) k1_quant_hist(const float* __restrict__ x) {
    extern __shared__ int sh[];             // NBF bins
    const int s     = blockIdx.x >> 2;
    const int chunk = blockIdx.x & (BPS1 - 1);
    const int t     = threadIdx.x;

    for (int i = t; i < NBF; i += TPB1) sh[i] = 0;
    __syncthreads();

    const int base = s * HW + chunk * PXB1;
    const float4* __restrict__ xin = (const float4*)x;
    const float third = 1.0f / 3.0f;

#pragma unroll 3
    for (int it = 0; it < ITER1; ++it) {
        int p  = base + it * (TPB1 * 4) + t * 4;
        int f4 = (p * 3) >> 2;
        float4 a = __ldcs(xin + f4 + 0);   // stream x: don't pollute L2
        float4 b = __ldcs(xin + f4 + 1);
        float4 c = __ldcs(xin + f4 + 2);

        uint32_t q0 = min((uint32_t)((a.x + a.y + a.z) * third * QSCALE + 0.5f), 65535u);
        uint32_t q1 = min((uint32_t)((a.w + b.x + b.y) * third * QSCALE + 0.5f), 65535u);
        uint32_t q2 = min((uint32_t)((b.z + b.w + c.x) * third * QSCALE + 0.5f), 65535u);
        uint32_t q3 = min((uint32_t)((c.y + c.z + c.w) * third * QSCALE + 0.5f), 65535u);

        uint2 w; w.x = q0 | (q1 << 16); w.y = q2 | (q3 << 16);
        ((uint2*)g_xq)[p >> 2] = w;        // retain in L2 for K5

        atomicAdd(&sh[q0 >> 2], 1);
        atomicAdd(&sh[q1 >> 2], 1);
        atomicAdd(&sh[q2 >> 2], 1);
        atomicAdd(&sh[q3 >> 2], 1);
    }
    __syncthreads();

    int* gh = &g_hist[s * NBF];
    for (int i = t; i < NBF; i += TPB1) {
        int v = sh[i];
        if (v) atomicAdd(&gh[i], v);       // result unused -> REDG
    }
}

// ---- k2: scan fine hist, interpolate quantiles, self-clean ------------------
__global__ void __launch_bounds__(1024) k2_scan_interp() {
    __shared__ int s_warp[32];
    __shared__ float s_v[4];
    const int s = blockIdx.x;
    const int t = threadIdx.x;
    const int lane = t & 31;
    const int wid  = t >> 5;
    const int CH = NBF / 1024;              // 16 bins per thread

    int* gh = &g_hist[s * NBF];
    int cnt[CH];
    int local = 0;
#pragma unroll
    for (int j = 0; j < CH / 4; j++) {
        int4 cw = *(int4*)(gh + 4 * (t * (CH / 4) + j) + 0);
        // NOTE: layout below keeps each thread's 16 bins contiguous:
        cnt[4 * j + 0] = cw.x; cnt[4 * j + 1] = cw.y;
        cnt[4 * j + 2] = cw.z; cnt[4 * j + 3] = cw.w;
        local += cw.x + cw.y + cw.z + cw.w;
    }
#pragma unroll
    for (int j = 0; j < CH / 4; j++)        // self-clean for graph replay
        *(int4*)(gh + 4 * (t * (CH / 4) + j)) = make_int4(0, 0, 0, 0);

    int v = local;
#pragma unroll
    for (int o = 1; o < 32; o <<= 1) {
        int n = __shfl_up_sync(0xFFFFFFFFu, v, o);
        if (lane >= o) v += n;
    }
    if (lane == 31) s_warp[wid] = v;
    __syncthreads();
    if (wid == 0) {
        int wv = s_warp[lane];
#pragma unroll
        for (int o = 1; o < 32; o <<= 1) {
            int n = __shfl_up_sync(0xFFFFFFFFu, wv, o);
            if (lane >= o) wv += n;
        }
        s_warp[lane] = wv;
    }
    __syncthreads();
    int cum = (v - local) + (wid ? s_warp[wid - 1] : 0);

    // locate 4 target ranks; interpolate value within bin (u16-value units)
    const int targets[4] = {KL, KL + 1, KH, KH + 1};
    const int base = t * CH;
    const float BW = 65536.0f / (float)NBF;   // 4.0 u16-units per bin
#pragma unroll
    for (int i = 0; i < CH; i++) {
        int c = cnt[i];
#pragma unroll
        for (int k = 0; k < 4; k++) {
            int r = targets[k];
            if (cum <= r && r < cum + c)
                s_v[k] = ((float)(base + i) + ((float)(r - cum) + 0.5f) / (float)c) * BW;
        }
        cum += c;
    }
    __syncthreads();

    if (t == 0) {
        float loQ = 0.5f * (s_v[0] + s_v[1]);
        float hiQ = 0.5f * (s_v[2] + s_v[3]);
        float rngQ = fmaxf(hiQ - loQ, 1e-6f * QSCALE);
        g_ab[s] = make_float2(loQ, 1.0f / rngQ);
    }
}

// ---- K5: normalize + clip; xq read mostly L2-hot, streamed output ----------
__global__ void __launch_bounds__(TPB5) k5_norm(float* __restrict__ out) {
    const int s     = blockIdx.x / BPS5;
    const int chunk = blockIdx.x % BPS5;
    const int t     = threadIdx.x;

    float2 ab = g_ab[s];
    const float loQ  = ab.x;
    const float invQ = ab.y;

    const uint2* __restrict__ xq2 =
        (const uint2*)g_xq + (size_t)s * (HW / 4) + chunk * (TPB5 * F4PT);
    float4* __restrict__ o4 =
        (float4*)out + (size_t)s * (HW / 4) + chunk * (TPB5 * F4PT);

#pragma unroll
    for (int k = 0; k < F4PT; k++) {
        uint2 w = __ldcs(xq2 + k * TPB5 + t);   // last use of xq
        float4 r;
        r.x = __saturatef(((float)(w.x & 0xFFFFu) - loQ) * invQ);
        r.y = __saturatef(((float)(w.x >> 16)     - loQ) * invQ);
        r.z = __saturatef(((float)(w.y & 0xFFFFu) - loQ) * invQ);
        r.w = __saturatef(((float)(w.y >> 16)     - loQ) * invQ);
        __stcs(o4 + k * TPB5 + t, r);
    }
}

// ---------------- launch ----------------
extern "C" void kernel_launch(void* const* d_in, const int* in_sizes, int n_in,
                              void* d_out, int out_size) {
    const float* x = (const float*)d_in[0];
    float* out = (float*)d_out;

    cudaFuncSetAttribute(k1_quant_hist, cudaFuncAttributeMaxDynamicSharedMemorySize, SMEM_H);
    k1_quant_hist<<<BATCH * BPS1, TPB1, SMEM_H>>>(x);
    k2_scan_interp<<<BATCH, 1024>>>();
    k5_norm<<<BATCH * BPS5, TPB5>>>(out);
}